// round 13
// baseline (speedup 1.0000x reference)
#include <cuda_runtime.h>
#include <cuda_fp16.h>
#include <cstdint>

// LSTM_36318243455658 — HMMA batched LSTM, B-fragments register-resident.
// CTA = 128 rows, 512 threads = 16 warps = 4 row-groups x 4 n-warps.
// Group gi owns rows 32gi..32gi+31 (two m16 row-tiles); warp cj in the group
// owns tile-pairs {3cj..} (cj<3: 3 pairs, cj=3: 4 pairs). B fragments are
// loaded into registers ONCE before the time loop (they were 88% of smem
// crossbar traffic). Per step: 2 row-tiles x pairs MMAs from reg-B + smem-A,
// f16x2 activations, fp32 c, h written to the other A buffer. One 128-thread
// named barrier per group per step. Numerically identical to the R12 kernel.

#define TT    2048
#define NB    16384
#define ROWS  128
#define NCTA  (NB / ROWS)
#define TPB   512
#define SA    56            // halves per A row (112B stride, conflict-free)
#define SB    56
#define NPAD  208
#define ABUF  (ROWS * SA)   // 7168 halves per A buffer
#define BSZ   (NPAD * SB)   // 11648 halves
#define SMEM_BYTES (2*ABUF*2 + BSZ*2 + 52*4 + 512*4)   // 54224 B

__device__ __forceinline__ uint32_t lds32(const half* p) {
    return *reinterpret_cast<const uint32_t*>(p);
}

__device__ __forceinline__ void mma16816(float& d0, float& d1, float& d2, float& d3,
                                         uint32_t a0, uint32_t a1, uint32_t a2, uint32_t a3,
                                         uint32_t b0, uint32_t b1) {
    asm volatile(
        "mma.sync.aligned.m16n8k16.row.col.f32.f16.f16.f32 "
        "{%0,%1,%2,%3}, {%4,%5,%6,%7}, {%8,%9}, {%0,%1,%2,%3};"
        : "+f"(d0), "+f"(d1), "+f"(d2), "+f"(d3)
        : "r"(a0), "r"(a1), "r"(a2), "r"(a3), "r"(b0), "r"(b1));
}
__device__ __forceinline__ void mma16808(float& d0, float& d1, float& d2, float& d3,
                                         uint32_t a0, uint32_t a1, uint32_t b0) {
    asm volatile(
        "mma.sync.aligned.m16n8k8.row.col.f32.f16.f16.f32 "
        "{%0,%1,%2,%3}, {%4,%5}, {%6}, {%0,%1,%2,%3};"
        : "+f"(d0), "+f"(d1), "+f"(d2), "+f"(d3)
        : "r"(a0), "r"(a1), "r"(b0));
}

__device__ __forceinline__ half2 tanh2(half2 v) {
    uint32_t u = *reinterpret_cast<uint32_t*>(&v), y;
    asm("tanh.approx.f16x2 %0, %1;" : "=r"(y) : "r"(u));
    return *reinterpret_cast<half2*>(&y);
}

// Entire time loop, templated on the number of owned tile-pairs so the
// register-resident B fragments have compile-time indices.
template<int NP>
__device__ __forceinline__ void run_loop(
    const half* __restrict__ A0, const half* __restrict__ A1,
    const half* __restrict__ Bs, const float* __restrict__ FC,
    float* __restrict__ sPart,
    const float* __restrict__ xlane, bool doX,
    int m0, int gi, int cj, int g, int tg, int barid)
{
    const int rowb0 = gi * 32;
    const half* bBase = Bs + g * SB + tg * 2;

    // ---- B fragments -> registers (once) ----
    uint32_t Bf[NP * 14];
#pragma unroll
    for (int q = 0; q < NP; q++) {
        const half* bp0 = bBase + (2 * (m0 + q)) * 8 * SB;   // (i,f)
        const half* bp1 = bp0 + 8 * SB;                      // (g,o)
#pragma unroll
        for (int kc = 0; kc < 3; kc++) {
            Bf[q * 14 + 2 * kc]     = lds32(bp0 + kc * 16);
            Bf[q * 14 + 2 * kc + 1] = lds32(bp0 + kc * 16 + 8);
            Bf[q * 14 + 7 + 2 * kc]     = lds32(bp1 + kc * 16);
            Bf[q * 14 + 7 + 2 * kc + 1] = lds32(bp1 + kc * 16 + 8);
        }
        Bf[q * 14 + 6]  = lds32(bp0 + 48);
        Bf[q * 14 + 13] = lds32(bp1 + 48);
    }

    float c[2][2 * NP];
#pragma unroll
    for (int i = 0; i < 2; i++)
#pragma unroll
        for (int k = 0; k < 2 * NP; k++) c[i][k] = 0.0f;
    float facc[4] = {0.f, 0.f, 0.f, 0.f};

    const half2 H05 = __floats2half2_rn(0.5f, 0.5f);

#pragma unroll 1
    for (int t = 0; t < TT; t++) {
        const half* rb = (t & 1) ? A1 : A0;
        half*       wn = const_cast<half*>((t & 1) ? A0 : A1);

        float xn = 0.0f;
        if (doX) {
            int tn = t + 1; if (tn >= TT) tn = TT - 1;
            xn = __ldg(xlane + tn);
        }
        const bool last = (t == TT - 1);

#pragma unroll
        for (int rt = 0; rt < 2; rt++) {
            const int rowb = rowb0 + 16 * rt;
            const half* p = rb + (rowb + g) * SA + tg * 2;

            uint32_t a16[3][4];
#pragma unroll
            for (int kc = 0; kc < 3; kc++) {
                a16[kc][0] = lds32(p + kc * 16);
                a16[kc][1] = lds32(p + kc * 16 + 8 * SA);
                a16[kc][2] = lds32(p + kc * 16 + 8);
                a16[kc][3] = lds32(p + kc * 16 + 8 * SA + 8);
            }
            uint32_t a8a = lds32(p + 48), a8b = lds32(p + 48 + 8 * SA);

            const int hG  = (rowb + g) * SA;
            const int hG8 = (rowb + g + 8) * SA;

#pragma unroll
            for (int q = 0; q < NP; q++) {
                float d0 = 0.f, d1 = 0.f, d2 = 0.f, d3 = 0.f;
                float e0 = 0.f, e1 = 0.f, e2 = 0.f, e3 = 0.f;
#pragma unroll
                for (int kc = 0; kc < 3; kc++) {
                    mma16816(d0, d1, d2, d3,
                             a16[kc][0], a16[kc][1], a16[kc][2], a16[kc][3],
                             Bf[q * 14 + 2 * kc], Bf[q * 14 + 2 * kc + 1]);
                    mma16816(e0, e1, e2, e3,
                             a16[kc][0], a16[kc][1], a16[kc][2], a16[kc][3],
                             Bf[q * 14 + 7 + 2 * kc], Bf[q * 14 + 7 + 2 * kc + 1]);
                }
                mma16808(d0, d1, d2, d3, a8a, a8b, Bf[q * 14 + 6]);
                mma16808(e0, e1, e2, e3, a8a, a8b, Bf[q * 14 + 13]);

                half2 I2 = tanh2(__floats2half2_rn(d0, d2));
                half2 F2 = tanh2(__floats2half2_rn(d1, d3));
                half2 G2 = tanh2(__floats2half2_rn(e0, e2));
                half2 O2 = tanh2(__floats2half2_rn(e1, e3));
                I2 = __hfma2(I2, H05, H05);
                F2 = __hfma2(F2, H05, H05);
                O2 = __hfma2(O2, H05, H05);
                half2 IG = __hmul2(I2, G2);

                float cn0 = fmaf(__low2float(F2),  c[rt][2 * q],     __low2float(IG));
                float cn1 = fmaf(__high2float(F2), c[rt][2 * q + 1], __high2float(IG));
                c[rt][2 * q]     = cn0;
                c[rt][2 * q + 1] = cn1;
                half2 T2 = tanh2(__floats2half2_rn(cn0, cn1));
                half2 H2 = __hmul2(O2, T2);

                const int j = 4 * (m0 + q) + tg;
                wn[hG  + j] = __low2half(H2);
                wn[hG8 + j] = __high2half(H2);
                if (last) {
                    float w = FC[j];
                    facc[rt * 2]     = fmaf(__low2float(H2),  w, facc[rt * 2]);
                    facc[rt * 2 + 1] = fmaf(__high2float(H2), w, facc[rt * 2 + 1]);
                }
            }
        }

        if (doX)
            wn[(rowb0 + (tg * 8 + g)) * SA + 52] = __float2half_rn(xn);

        asm volatile("bar.sync %0, %1;" :: "r"(barid), "n"(128) : "memory");
    }

    // fc partials: sum over tg lanes (disjoint j, same rows)
#pragma unroll
    for (int i = 0; i < 4; i++) {
        facc[i] += __shfl_xor_sync(0xffffffffu, facc[i], 1);
        facc[i] += __shfl_xor_sync(0xffffffffu, facc[i], 2);
    }
    if (tg == 0) {
        sPart[cj * ROWS + rowb0 + g]      = facc[0];
        sPart[cj * ROWS + rowb0 + g + 8]  = facc[1];
        sPart[cj * ROWS + rowb0 + g + 16] = facc[2];
        sPart[cj * ROWS + rowb0 + g + 24] = facc[3];
    }
}

__global__ void __launch_bounds__(TPB, 1)
lstm_mma4_kernel(const float* __restrict__ x,
                 const float* __restrict__ w_ih,
                 const float* __restrict__ w_hh,
                 const float* __restrict__ b_ih,
                 const float* __restrict__ b_hh,
                 const float* __restrict__ w_fc,
                 const float* __restrict__ b_fc,
                 float* __restrict__ out)
{
    extern __shared__ __align__(16) char dsmem[];
    half*  A0    = (half*)dsmem;
    half*  A1    = A0 + ABUF;
    half*  Bs    = A1 + ABUF;
    float* FC    = (float*)(Bs + BSZ);
    float* sPart = FC + 52;

    const int tid  = threadIdx.x;
    const int wid  = tid >> 5;
    const int lane = tid & 31;
    const int g    = lane >> 2;
    const int tg   = lane & 3;
    const int gi   = wid >> 2;          // row-group 0..3 (32 rows each)
    const int cj   = wid & 3;           // n-warp 0..3
    const int barid = 1 + gi;
    const long long ctabase = (long long)blockIdx.x * ROWS;

    // ---- staging (identical layout/values to R12 kernel) ----
    for (int i = tid; i < ABUF; i += TPB)
        reinterpret_cast<uint32_t*>(A0)[i] = 0u;     // zero both A buffers
    for (int i = tid; i < BSZ; i += TPB) {
        int n = i / SB, k = i - n * SB;
        int nt = n >> 3, par = nt & 1, mI = nt >> 1, cc = n & 7;
        int u = cc >> 1, bsel = cc & 1;
        int j = 4 * mI + u;
        int gt = par ? (bsel ? 3 : 2) : (bsel ? 1 : 0);   // i,f | g,o
        float v = 0.0f;
        if (j < 50) {
            int orig = gt * 50 + j;
            if (k < 50)       v = w_hh[orig * 50 + k];
            else if (k == 52) v = w_ih[orig];
            else if (k == 53) v = b_ih[orig] + b_hh[orig];
            if (gt != 2) v *= 0.5f;
        }
        Bs[i] = __float2half_rn(v);
    }
    if (tid < 52) FC[tid] = (tid < 50) ? w_fc[tid] : 0.0f;
    __syncthreads();
    if (tid < ROWS) {
        float x0 = __ldg(x + (ctabase + tid) * TT);
        A0[tid * SA + 52] = __float2half_rn(x0);
        A0[tid * SA + 53] = __float2half_rn(1.0f);
        A1[tid * SA + 53] = __float2half_rn(1.0f);
    }
    __syncthreads();

    // x prefetch owner: cj==0 warp, lane maps to its group's 32 rows
    const float* xlane = x + (ctabase + gi * 32 + (tg * 8 + g)) * TT;
    const bool doX = (cj == 0);

    if (cj == 3)
        run_loop<4>(A0, A1, Bs, FC, sPart, xlane, doX, 9, gi, cj, g, tg, barid);
    else
        run_loop<3>(A0, A1, Bs, FC, sPart, xlane, doX, 3 * cj, gi, cj, g, tg, barid);

    __syncthreads();
    if (tid < ROWS)
        out[ctabase + tid] = sPart[tid] + sPart[ROWS + tid] +
                             sPart[2 * ROWS + tid] + sPart[3 * ROWS + tid] +
                             __ldg(b_fc);
}

extern "C" void kernel_launch(void* const* d_in, const int* in_sizes, int n_in,
                              void* d_out, int out_size) {
    const float* x    = (const float*)d_in[0];
    const float* w_ih = (const float*)d_in[1];
    const float* w_hh = (const float*)d_in[2];
    const float* b_ih = (const float*)d_in[3];
    const float* b_hh = (const float*)d_in[4];
    const float* w_fc = (const float*)d_in[5];
    const float* b_fc = (const float*)d_in[6];

    cudaFuncSetAttribute(lstm_mma4_kernel,
                         cudaFuncAttributeMaxDynamicSharedMemorySize,
                         SMEM_BYTES);
    lstm_mma4_kernel<<<NCTA, TPB, SMEM_BYTES>>>(x, w_ih, w_hh, b_ih, b_hh,
                                                w_fc, b_fc, (float*)d_out);
}

// round 17
// speedup vs baseline: 1.2792x; 1.2792x over previous
#include <cuda_runtime.h>
#include <cuda_fp16.h>
#include <cstdint>

// LSTM_36318243455658 — HMMA batched LSTM, balanced unit split + streaming B.
// CTA = 128 rows, 512 threads = 16 warps = 4 row-groups(32 rows) x 4 n-warps.
// Unit = (row-tile, tile-pair); 26 units/group split {7,7,6,6}:
// cj0 = pairs{0,1,2}x2rt + (pair3,rt0); cj1 = pairs{4,5,6}x2rt + (pair3,rt1);
// cj2 = pairs{7,8,9}x2rt; cj3 = pairs{10,11,12}x2rt + x-prefetch.
// B streams through 14 transient regs per pair (reused across both row-tiles):
// B-LDS per warp-step 182 -> ~49. A frags for both row-tiles held live.
// One 128-thread named barrier per group per step. Math identical to R12.

#define TT    2048
#define NB    16384
#define ROWS  128
#define NCTA  (NB / ROWS)
#define TPB   512
#define SA    56
#define SB    56
#define NPAD  208
#define ABUF  (ROWS * SA)
#define BSZ   (NPAD * SB)
#define SMEM_BYTES (2*ABUF*2 + BSZ*2 + 52*4 + 512*4)

#define EXTRA_PAIR 3

__device__ __forceinline__ uint32_t lds32(const half* p) {
    return *reinterpret_cast<const uint32_t*>(p);
}

__device__ __forceinline__ void mma16816(float& d0, float& d1, float& d2, float& d3,
                                         uint32_t a0, uint32_t a1, uint32_t a2, uint32_t a3,
                                         uint32_t b0, uint32_t b1) {
    asm volatile(
        "mma.sync.aligned.m16n8k16.row.col.f32.f16.f16.f32 "
        "{%0,%1,%2,%3}, {%4,%5,%6,%7}, {%8,%9}, {%0,%1,%2,%3};"
        : "+f"(d0), "+f"(d1), "+f"(d2), "+f"(d3)
        : "r"(a0), "r"(a1), "r"(a2), "r"(a3), "r"(b0), "r"(b1));
}
__device__ __forceinline__ void mma16808(float& d0, float& d1, float& d2, float& d3,
                                         uint32_t a0, uint32_t a1, uint32_t b0) {
    asm volatile(
        "mma.sync.aligned.m16n8k8.row.col.f32.f16.f16.f32 "
        "{%0,%1,%2,%3}, {%4,%5}, {%6}, {%0,%1,%2,%3};"
        : "+f"(d0), "+f"(d1), "+f"(d2), "+f"(d3)
        : "r"(a0), "r"(a1), "r"(b0));
}

__device__ __forceinline__ half2 tanh2(half2 v) {
    uint32_t u = *reinterpret_cast<uint32_t*>(&v), y;
    asm("tanh.approx.f16x2 %0, %1;" : "=r"(y) : "r"(u));
    return *reinterpret_cast<half2*>(&y);
}

__device__ __forceinline__ void loadB(uint32_t* Bf, const half* bBase, int m) {
    const half* bp0 = bBase + (2 * m) * 8 * SB;
    const half* bp1 = bp0 + 8 * SB;
#pragma unroll
    for (int kc = 0; kc < 3; kc++) {
        Bf[2 * kc]         = lds32(bp0 + kc * 16);
        Bf[2 * kc + 1]     = lds32(bp0 + kc * 16 + 8);
        Bf[7 + 2 * kc]     = lds32(bp1 + kc * 16);
        Bf[7 + 2 * kc + 1] = lds32(bp1 + kc * 16 + 8);
    }
    Bf[6]  = lds32(bp0 + 48);
    Bf[13] = lds32(bp1 + 48);
}

__device__ __forceinline__ void do_unit(
    const uint32_t* Bf, const uint32_t* aF,
    float& cc0, float& cc1, half* wn, int hG, int hG8, int j,
    bool last, float& fL, float& fH, const float* FC)
{
    const half2 H05 = __floats2half2_rn(0.5f, 0.5f);
    float d0 = 0.f, d1 = 0.f, d2 = 0.f, d3 = 0.f;
    float e0 = 0.f, e1 = 0.f, e2 = 0.f, e3 = 0.f;
#pragma unroll
    for (int kc = 0; kc < 3; kc++) {
        mma16816(d0, d1, d2, d3,
                 aF[4 * kc], aF[4 * kc + 1], aF[4 * kc + 2], aF[4 * kc + 3],
                 Bf[2 * kc], Bf[2 * kc + 1]);
        mma16816(e0, e1, e2, e3,
                 aF[4 * kc], aF[4 * kc + 1], aF[4 * kc + 2], aF[4 * kc + 3],
                 Bf[7 + 2 * kc], Bf[7 + 2 * kc + 1]);
    }
    mma16808(d0, d1, d2, d3, aF[12], aF[13], Bf[6]);
    mma16808(e0, e1, e2, e3, aF[12], aF[13], Bf[13]);

    half2 I2 = tanh2(__floats2half2_rn(d0, d2));
    half2 F2 = tanh2(__floats2half2_rn(d1, d3));
    half2 G2 = tanh2(__floats2half2_rn(e0, e2));
    half2 O2 = tanh2(__floats2half2_rn(e1, e3));
    I2 = __hfma2(I2, H05, H05);
    F2 = __hfma2(F2, H05, H05);
    O2 = __hfma2(O2, H05, H05);
    half2 IG = __hmul2(I2, G2);

    float cn0 = fmaf(__low2float(F2),  cc0, __low2float(IG));
    float cn1 = fmaf(__high2float(F2), cc1, __high2float(IG));
    cc0 = cn0;
    cc1 = cn1;
    half2 T2 = tanh2(__floats2half2_rn(cn0, cn1));
    half2 H2 = __hmul2(O2, T2);

    wn[hG  + j] = __low2half(H2);
    wn[hG8 + j] = __high2half(H2);
    if (last) {
        float w = FC[j];
        fL = fmaf(__low2float(H2),  w, fL);
        fH = fmaf(__high2float(H2), w, fH);
    }
}

template<int NF, int EXTRA_RT>
__device__ __forceinline__ void run_loop(
    const half* __restrict__ A0, const half* __restrict__ A1,
    const half* __restrict__ Bs, const float* __restrict__ FC,
    float* __restrict__ sPart,
    const float* __restrict__ xlane, bool doX,
    int m0, int gi, int cj, int g, int tg, int barid)
{
    const int rowb0 = gi * 32;
    const half* bBase = Bs + g * SB + tg * 2;

    // c state: [pair q][row-tile rt][half] -> c[(q*2+rt)*2 + half]; +2 for extra
    float c[4 * NF + 2];
#pragma unroll
    for (int k = 0; k < 4 * NF + 2; k++) c[k] = 0.0f;
    float facc[4] = {0.f, 0.f, 0.f, 0.f};

#pragma unroll 1
    for (int t = 0; t < TT; t++) {
        const half* rb = (t & 1) ? A1 : A0;
        half*       wn = const_cast<half*>((t & 1) ? A0 : A1);

        float xn = 0.0f;
        if (doX) {
            int tn = t + 1; if (tn >= TT) tn = TT - 1;
            xn = __ldg(xlane + tn);
        }
        const bool last = (t == TT - 1);

        uint32_t aF[2][14];
        int hG[2], hG8[2];
#pragma unroll
        for (int rt = 0; rt < 2; rt++) {
            const int rowb = rowb0 + 16 * rt;
            const half* p = rb + (rowb + g) * SA + tg * 2;
#pragma unroll
            for (int kc = 0; kc < 3; kc++) {
                aF[rt][4 * kc]     = lds32(p + kc * 16);
                aF[rt][4 * kc + 1] = lds32(p + kc * 16 + 8 * SA);
                aF[rt][4 * kc + 2] = lds32(p + kc * 16 + 8);
                aF[rt][4 * kc + 3] = lds32(p + kc * 16 + 8 * SA + 8);
            }
            aF[rt][12] = lds32(p + 48);
            aF[rt][13] = lds32(p + 48 + 8 * SA);
            hG[rt]  = (rowb + g) * SA;
            hG8[rt] = (rowb + g + 8) * SA;
        }

#pragma unroll
        for (int q = 0; q < NF; q++) {
            const int m = m0 + q;
            uint32_t Bf[14];
            loadB(Bf, bBase, m);
            const int j = 4 * m + tg;
            do_unit(Bf, aF[0], c[(q * 2) * 2], c[(q * 2) * 2 + 1], wn,
                    hG[0], hG8[0], j, last, facc[0], facc[1], FC);
            do_unit(Bf, aF[1], c[(q * 2 + 1) * 2], c[(q * 2 + 1) * 2 + 1], wn,
                    hG[1], hG8[1], j, last, facc[2], facc[3], FC);
        }

        if (EXTRA_RT >= 0) {
            uint32_t Bf[14];
            loadB(Bf, bBase, EXTRA_PAIR);
            const int j = 4 * EXTRA_PAIR + tg;
            do_unit(Bf, aF[EXTRA_RT], c[4 * NF], c[4 * NF + 1], wn,
                    hG[EXTRA_RT], hG8[EXTRA_RT], j, last,
                    facc[EXTRA_RT * 2], facc[EXTRA_RT * 2 + 1], FC);
        }

        if (doX)
            wn[(rowb0 + (tg * 8 + g)) * SA + 52] = __float2half_rn(xn);

        asm volatile("bar.sync %0, %1;" :: "r"(barid), "n"(128) : "memory");
    }

#pragma unroll
    for (int i = 0; i < 4; i++) {
        facc[i] += __shfl_xor_sync(0xffffffffu, facc[i], 1);
        facc[i] += __shfl_xor_sync(0xffffffffu, facc[i], 2);
    }
    if (tg == 0) {
        sPart[cj * ROWS + rowb0 + g]      = facc[0];
        sPart[cj * ROWS + rowb0 + g + 8]  = facc[1];
        sPart[cj * ROWS + rowb0 + g + 16] = facc[2];
        sPart[cj * ROWS + rowb0 + g + 24] = facc[3];
    }
}

__global__ void __launch_bounds__(TPB, 1)
lstm_mma5_kernel(const float* __restrict__ x,
                 const float* __restrict__ w_ih,
                 const float* __restrict__ w_hh,
                 const float* __restrict__ b_ih,
                 const float* __restrict__ b_hh,
                 const float* __restrict__ w_fc,
                 const float* __restrict__ b_fc,
                 float* __restrict__ out)
{
    extern __shared__ __align__(16) char dsmem[];
    half*  A0    = (half*)dsmem;
    half*  A1    = A0 + ABUF;
    half*  Bs    = A1 + ABUF;
    float* FC    = (float*)(Bs + BSZ);
    float* sPart = FC + 52;

    const int tid  = threadIdx.x;
    const int wid  = tid >> 5;
    const int lane = tid & 31;
    const int g    = lane >> 2;
    const int tg   = lane & 3;
    const int gi   = wid >> 2;
    const int cj   = wid & 3;
    const int barid = 1 + gi;
    const long long ctabase = (long long)blockIdx.x * ROWS;

    for (int i = tid; i < ABUF; i += TPB)
        reinterpret_cast<uint32_t*>(A0)[i] = 0u;
    for (int i = tid; i < BSZ; i += TPB) {
        int n = i / SB, k = i - n * SB;
        int nt = n >> 3, par = nt & 1, mI = nt >> 1, cc = n & 7;
        int u = cc >> 1, bsel = cc & 1;
        int j = 4 * mI + u;
        int gt = par ? (bsel ? 3 : 2) : (bsel ? 1 : 0);
        float v = 0.0f;
        if (j < 50) {
            int orig = gt * 50 + j;
            if (k < 50)       v = w_hh[orig * 50 + k];
            else if (k == 52) v = w_ih[orig];
            else if (k == 53) v = b_ih[orig] + b_hh[orig];
            if (gt != 2) v *= 0.5f;
        }
        Bs[i] = __float2half_rn(v);
    }
    if (tid < 52) FC[tid] = (tid < 50) ? w_fc[tid] : 0.0f;
    __syncthreads();
    if (tid < ROWS) {
        float x0 = __ldg(x + (ctabase + tid) * TT);
        A0[tid * SA + 52] = __float2half_rn(x0);
        A0[tid * SA + 53] = __float2half_rn(1.0f);
        A1[tid * SA + 53] = __float2half_rn(1.0f);
    }
    __syncthreads();

    const float* xlane = x + (ctabase + gi * 32 + (tg * 8 + g)) * TT;

    if (cj == 0)
        run_loop<3, 0>(A0, A1, Bs, FC, sPart, xlane, false, 0, gi, cj, g, tg, barid);
    else if (cj == 1)
        run_loop<3, 1>(A0, A1, Bs, FC, sPart, xlane, false, 4, gi, cj, g, tg, barid);
    else if (cj == 2)
        run_loop<3, -1>(A0, A1, Bs, FC, sPart, xlane, false, 7, gi, cj, g, tg, barid);
    else
        run_loop<3, -1>(A0, A1, Bs, FC, sPart, xlane, true, 10, gi, cj, g, tg, barid);

    __syncthreads();
    if (tid < ROWS)
        out[ctabase + tid] = sPart[tid] + sPart[ROWS + tid] +
                             sPart[2 * ROWS + tid] + sPart[3 * ROWS + tid] +
                             __ldg(b_fc);
}

extern "C" void kernel_launch(void* const* d_in, const int* in_sizes, int n_in,
                              void* d_out, int out_size) {
    const float* x    = (const float*)d_in[0];
    const float* w_ih = (const float*)d_in[1];
    const float* w_hh = (const float*)d_in[2];
    const float* b_ih = (const float*)d_in[3];
    const float* b_hh = (const float*)d_in[4];
    const float* w_fc = (const float*)d_in[5];
    const float* b_fc = (const float*)d_in[6];

    cudaFuncSetAttribute(lstm_mma5_kernel,
                         cudaFuncAttributeMaxDynamicSharedMemorySize,
                         SMEM_BYTES);
    lstm_mma5_kernel<<<NCTA, TPB, SMEM_BYTES>>>(x, w_ih, w_hh, b_ih, b_hh,
                                                w_fc, b_fc, (float*)d_out);
}